// round 2
// baseline (speedup 1.0000x reference)
#include <cuda_runtime.h>
#include <math.h>

// Problem dims
#define B 8
#define S 4096
#define F 128
#define T 16
#define THRESH 0.1f
#define EPS 1e-8f

#define NCHUNK 16            // s-chunks for the stats pass (256 rows each)
#define RUN 32               // consecutive s-rows per thread in k_acc

// Scratch: per-chunk partial sums (no atomics, no zeroing needed) + inv-std
__device__ float g_p1[NCHUNK][B * F];
__device__ float g_p2[NCHUNK][B * F];
__device__ __align__(16) float g_inv[B * F];

// Stats pass: each thread owns RUN consecutive s-rows, rolls cur->prev in
// registers (33 loads per 32 diffs). block (128 f, 8 s-threads), grid (16, B).
__global__ void k_acc(const float* __restrict__ x) {
    int f  = threadIdx.x;     // 0..127
    int ty = threadIdx.y;     // 0..7
    int chunk = blockIdx.x;   // 0..15
    int b = blockIdx.y;

    const float* base = x + (size_t)b * S * F;
    int s_start = chunk * (8 * RUN) + ty * RUN;

    // prepend semantics: diff[0] = 0
    float prev = (s_start == 0) ? base[f] : base[(size_t)(s_start - 1) * F + f];

    float s1 = 0.f, s2 = 0.f;
    #pragma unroll 8
    for (int j = 0; j < RUN; j++) {
        float cur = base[(size_t)(s_start + j) * F + f];
        float d = cur - prev;
        s1 += d;
        s2 += d * d;
        prev = cur;
    }

    __shared__ float sh1[8][128];
    __shared__ float sh2[8][128];
    sh1[ty][f] = s1;
    sh2[ty][f] = s2;
    __syncthreads();
    if (ty == 0) {
        float t1 = 0.f, t2 = 0.f;
        #pragma unroll
        for (int j = 0; j < 8; j++) { t1 += sh1[j][f]; t2 += sh2[j][f]; }
        g_p1[chunk][b * F + f] = t1;
        g_p2[chunk][b * F + f] = t2;
    }
}

__global__ void k_inv() {
    int i = blockIdx.x * blockDim.x + threadIdx.x;
    if (i < B * F) {
        double sum = 0.0, sumsq = 0.0;
        #pragma unroll
        for (int c = 0; c < NCHUNK; c++) {
            sum   += (double)g_p1[c][i];
            sumsq += (double)g_p2[c][i];
        }
        double m = sum / (double)S;
        double var = sumsq / (double)S - m * m;
        if (var < 0.0) var = 0.0;
        float sd = (float)sqrt(var);
        g_inv[i] = 1.0f / (sd + EPS);
    }
}

// Main expansion: one float4 per thread over B*S*F/4 elements.
// 16 coalesced streaming float4 stores per thread (phase pattern t%3).
__global__ void k_main(const float4* __restrict__ x, float4* __restrict__ out) {
    int i = blockIdx.x * blockDim.x + threadIdx.x;  // 0 .. B*S*(F/4)-1
    int f4 = i & 31;            // F/4 = 32
    int s  = (i >> 5) & 4095;
    int b  = i >> 17;

    float4 cur = x[i];
    float4 prv = (s == 0) ? cur : x[i - 32];

    const float4 inv4 = *reinterpret_cast<const float4*>(&g_inv[b * F + f4 * 4]);

    float ndx = (cur.x - prv.x) * inv4.x;
    float ndy = (cur.y - prv.y) * inv4.y;
    float ndz = (cur.z - prv.z) * inv4.z;
    float ndw = (cur.w - prv.w) * inv4.w;

    float4 pos, neg;
    const float4 zero = make_float4(0.f, 0.f, 0.f, 0.f);
    pos.x = (ndx >=  THRESH) ? 1.f : 0.f;
    pos.y = (ndy >=  THRESH) ? 1.f : 0.f;
    pos.z = (ndz >=  THRESH) ? 1.f : 0.f;
    pos.w = (ndw >=  THRESH) ? 1.f : 0.f;
    neg.x = (-ndx >= THRESH) ? 1.f : 0.f;
    neg.y = (-ndy >= THRESH) ? 1.f : 0.f;
    neg.z = (-ndz >= THRESH) ? 1.f : 0.f;
    neg.w = (-ndw >= THRESH) ? 1.f : 0.f;

    // out index (b,t,s,f4) = ((b*T + t)*S + s)*32 + f4
    const size_t tstride = (size_t)S * 32;
    size_t obase = ((size_t)b * T * S + s) * 32 + f4;

    #pragma unroll
    for (int t = 0; t < T; t++) {
        int ph = t % 3;
        float4 v = (ph == 0) ? pos : (ph == 1) ? neg : zero;
        __stcs(&out[obase + (size_t)t * tstride], v);
    }
}

extern "C" void kernel_launch(void* const* d_in, const int* in_sizes, int n_in,
                              void* d_out, int out_size) {
    const float* x = (const float*)d_in[0];
    float* out = (float*)d_out;

    dim3 bt(128, 8);
    dim3 gr(NCHUNK, B);
    k_acc<<<gr, bt>>>(x);
    k_inv<<<1, 1024>>>();

    int n4 = B * S * (F / 4);          // 1,048,576 float4 threads
    k_main<<<n4 / 256, 256>>>((const float4*)x, (float4*)out);
}